// round 10
// baseline (speedup 1.0000x reference)
#include <cuda_runtime.h>
#include <cuda_fp16.h>
#include <math.h>
#include <stdint.h>

#define TTOK 4096
#define DHID 1024
#define NEXP 64
#define IMOE 512
#define NPAIR 8192

// ---------------- scratch (static device globals) ----------------
__device__ int    g_off[NEXP + 1];
__device__ int    g_pe[NPAIR];
__device__ float  g_pw[NPAIR];
__device__ int    g_slot_tok[NPAIR];
__device__ int    g_pair_slot[NPAIR];
__device__ float  g_shgate[TTOK];
__device__ float  g_logits[TTOK * NEXP];
__device__ __half g_xh[TTOK * DHID];          // x in fp16         [4096,1024]
__device__ __half g_act[NPAIR * IMOE];        // routed activated  [8192,512] fp16
__device__ __half g_acts[TTOK * IMOE];        // shared activated  [4096,512] fp16
__device__ float  g_y[NPAIR * DHID];          // routed down out   [8192,1024]

// ---------------- helpers ----------------
__device__ __forceinline__ uint32_t smem_u32(const void* p) {
    uint32_t a;
    asm("{ .reg .u64 t; cvta.to.shared.u64 t, %1; cvt.u32.u64 %0, t; }" : "=r"(a) : "l"(p));
    return a;
}
__device__ __forceinline__ void cpa16h(uint32_t d, const __half* s) {
    asm volatile("cp.async.ca.shared.global [%0], [%1], 16;" :: "r"(d), "l"(s) : "memory");
}
__device__ __forceinline__ void cpcommit() {
    asm volatile("cp.async.commit_group;" ::: "memory");
}
__device__ __forceinline__ void ldsm4(uint32_t& d0, uint32_t& d1, uint32_t& d2, uint32_t& d3,
                                      uint32_t a) {
    asm volatile("ldmatrix.sync.aligned.m8n8.x4.shared.b16 {%0,%1,%2,%3}, [%4];"
                 : "=r"(d0), "=r"(d1), "=r"(d2), "=r"(d3) : "r"(a));
}
// D += A(m16k16 f16) * B(k16n8 f16), fp32 acc
__device__ __forceinline__ void mma16(float* c, const uint32_t* a, uint32_t b0, uint32_t b1) {
    asm volatile(
        "mma.sync.aligned.m16n8k16.row.col.f32.f16.f16.f32 "
        "{%0,%1,%2,%3}, {%4,%5,%6,%7}, {%8,%9}, {%0,%1,%2,%3};"
        : "+f"(c[0]), "+f"(c[1]), "+f"(c[2]), "+f"(c[3])
        : "r"(a[0]), "r"(a[1]), "r"(a[2]), "r"(a[3]), "r"(b0), "r"(b1));
}
__device__ __forceinline__ uint32_t h2u(__half2 h) {
    uint32_t u;
    memcpy(&u, &h, 4);
    return u;
}
__device__ __forceinline__ uint2 cvt4(float4 v) {
    __half2 h01 = __floats2half2_rn(v.x, v.y);
    __half2 h23 = __floats2half2_rn(v.z, v.w);
    return make_uint2(h2u(h01), h2u(h23));
}
__device__ __forceinline__ int imin(int a, int b) { return a < b ? a : b; }

// ---------------- pre/post kernels ----------------
__global__ void cvt_x_kernel(const float* __restrict__ x) {
    int i = blockIdx.x * 256 + threadIdx.x;      // index of float4 group
    float4 v = ((const float4*)x)[i];
    *(uint2*)&g_xh[(size_t)i * 4] = cvt4(v);
}

__global__ void softmax_topk_kernel(const float* __restrict__ x,
                                    const float* __restrict__ sheg,
                                    float* __restrict__ probs_out) {
    int w = threadIdx.x >> 5, lane = threadIdx.x & 31;
    int t = blockIdx.x * 8 + w;
    if (t >= TTOK) return;

    const float* xr = x + (size_t)t * DHID;
    float sd = 0.f;
    for (int k = lane; k < DHID; k += 32) sd += xr[k] * sheg[k];
    #pragma unroll
    for (int o = 16; o; o >>= 1) sd += __shfl_xor_sync(~0u, sd, o);
    if (lane == 0) g_shgate[t] = 1.f / (1.f + expf(-sd));

    float l0 = g_logits[t * 64 + lane];
    float l1 = g_logits[t * 64 + 32 + lane];
    float m = fmaxf(l0, l1);
    #pragma unroll
    for (int o = 16; o; o >>= 1) m = fmaxf(m, __shfl_xor_sync(~0u, m, o));
    float e0 = expf(l0 - m), e1 = expf(l1 - m);
    float s = e0 + e1;
    #pragma unroll
    for (int o = 16; o; o >>= 1) s += __shfl_xor_sync(~0u, s, o);
    float inv = 1.f / s;
    float p0 = e0 * inv, p1 = e1 * inv;
    if (probs_out) {
        probs_out[t * 64 + lane]      = p0;
        probs_out[t * 64 + 32 + lane] = p1;
    }
    float v0, v1; int i0, i1;
    if (p1 > p0) { v0 = p1; i0 = lane + 32; v1 = p0; i1 = lane; }
    else         { v0 = p0; i0 = lane;      v1 = p1; i1 = lane + 32; }
    #pragma unroll
    for (int o = 16; o; o >>= 1) {
        float w0 = __shfl_xor_sync(~0u, v0, o); int j0 = __shfl_xor_sync(~0u, i0, o);
        float w1 = __shfl_xor_sync(~0u, v1, o); int j1 = __shfl_xor_sync(~0u, i1, o);
        if (w0 > v0 || (w0 == v0 && j0 < i0)) { v1 = v0; i1 = i0; v0 = w0; i0 = j0;
            if (w1 > v1 || (w1 == v1 && j1 < i1)) { v1 = w1; i1 = j1; } }
        else if (w0 > v1 || (w0 == v1 && j0 < i1)) { v1 = w0; i1 = j0; }
    }
    if (lane == 0) {
        float inv2 = 1.f / (v0 + v1 + 1e-9f);
        int p = t * 2;
        g_pe[p] = i0;     g_pw[p] = v0 * inv2;
        g_pe[p + 1] = i1; g_pw[p + 1] = v1 * inv2;
    }
}

// single-block dispatch: histogram -> scan -> scatter slots
__global__ void dispatch_kernel() {
    __shared__ int cnt[NEXP];
    __shared__ int off[NEXP + 1];
    __shared__ int fill[NEXP];
    int tid = threadIdx.x;
    if (tid < NEXP) cnt[tid] = 0;
    __syncthreads();
    for (int p = tid; p < NPAIR; p += 1024) atomicAdd(&cnt[g_pe[p]], 1);
    __syncthreads();
    if (tid == 0) {
        int a = 0;
        for (int e = 0; e < NEXP; e++) { off[e] = a; fill[e] = a; a += cnt[e]; }
        off[NEXP] = a;
    }
    __syncthreads();
    if (tid <= NEXP) g_off[tid] = off[tid];
    for (int p = tid; p < NPAIR; p += 1024) {
        int s = atomicAdd(&fill[g_pe[p]], 1);
        g_slot_tok[s] = p >> 1;
        g_pair_slot[p] = s;
    }
}

// final combine: out[t] += w0*y[slot0] + w1*y[slot1]
__global__ void combine_kernel(float* __restrict__ out) {
    int w = threadIdx.x >> 5, lane = threadIdx.x & 31;
    int t = blockIdx.x * 8 + w;
    if (t >= TTOK) return;
    int s0 = g_pair_slot[2 * t], s1 = g_pair_slot[2 * t + 1];
    float w0 = g_pw[2 * t], w1 = g_pw[2 * t + 1];
    float4* o = (float4*)(out + (long)t * DHID);
    const float4* y0 = (const float4*)(g_y + (long)s0 * DHID);
    const float4* y1 = (const float4*)(g_y + (long)s1 * DHID);
    for (int i = lane; i < DHID / 4; i += 32) {
        float4 a = o[i], b = y0[i], c = y1[i];
        a.x += w0 * b.x + w1 * c.x;
        a.y += w0 * b.y + w1 * c.y;
        a.z += w0 * b.z + w1 * c.z;
        a.w += w0 * b.w + w1 * c.w;
        o[i] = a;
    }
}

// -------- fp32 SIMT GEMM for router logits (precision-critical) --------
__global__ void __launch_bounds__(256)
logits_gemm(const float* __restrict__ A, const float* __restrict__ B,
            float* __restrict__ C) {
    const int N = 64, Kd = 1024;
    __shared__ float As[32][33];
    __shared__ float Bs[32][65];
    int tid = threadIdx.x;
    int m0 = blockIdx.y * 32;
    int tx = tid & 15, ty = tid >> 4;

    int ar = tid >> 3, akc = (tid & 7) * 4;
    const float* Arow = A + (long)(m0 + ar) * Kd + akc;
    int br0 = tid >> 3;
    int bkc = (tid & 7) * 4;
    const float* Brow0 = B + (long)br0 * Kd + bkc;
    const float* Brow1 = B + (long)(br0 + 32) * Kd + bkc;

    float acc[2][4] = {};
    for (int k0 = 0; k0 < Kd; k0 += 32) {
        float4 av = *(const float4*)(Arow + k0);
        float4 bv0 = *(const float4*)(Brow0 + k0);
        float4 bv1 = *(const float4*)(Brow1 + k0);
        As[akc + 0][ar] = av.x; As[akc + 1][ar] = av.y;
        As[akc + 2][ar] = av.z; As[akc + 3][ar] = av.w;
        Bs[bkc + 0][br0] = bv0.x; Bs[bkc + 1][br0] = bv0.y;
        Bs[bkc + 2][br0] = bv0.z; Bs[bkc + 3][br0] = bv0.w;
        Bs[bkc + 0][br0 + 32] = bv1.x; Bs[bkc + 1][br0 + 32] = bv1.y;
        Bs[bkc + 2][br0 + 32] = bv1.z; Bs[bkc + 3][br0 + 32] = bv1.w;
        __syncthreads();
        #pragma unroll 8
        for (int kk = 0; kk < 32; kk++) {
            float a0 = As[kk][ty * 2], a1 = As[kk][ty * 2 + 1];
            #pragma unroll
            for (int j = 0; j < 4; j++) {
                float b = Bs[kk][tx * 4 + j];
                acc[0][j] += a0 * b;
                acc[1][j] += a1 * b;
            }
        }
        __syncthreads();
    }
    #pragma unroll
    for (int i = 0; i < 2; i++)
        #pragma unroll
        for (int j = 0; j < 4; j++)
            C[(long)(m0 + ty * 2 + i) * N + tx * 4 + j] = acc[i][j];
}

// ------- fp16 mma.sync GEMM, CTA 128x128, warp 32x64, BK=16 -------
// A source is fp16 in gmem -> cp.async 4-deep ring (no RF transit).
// B source is fp32 weights -> LDG + cvt + STS double buffer.
// MODE 0: shared gate/up fused (A=g_xh; B even=shg, odd=shu) -> g_acts (fp16)
// MODE 1: routed gate/up fused (A=g_xh via g_slot_tok; B=gate_up[e]) -> g_act (fp16)
// MODE 2: routed down (A=g_act slots, K=512; B=down[e]) -> g_y (fp32)
// MODE 3: shared down (A=g_acts, K=512; B=shd) -> out = shgate*v (fp32)
#define RS 24              // smem row stride in halves (48B)
#define BUFH (128 * RS)    // halves per buffer = 3072

template <int MODE>
__global__ void __launch_bounds__(256, 2)
mma_gemm(const __half* __restrict__ A, const float* __restrict__ B1,
         const float* __restrict__ B2, void* __restrict__ Cv) {
    constexpr int Kd  = (MODE == 0 || MODE == 1) ? 1024 : 512;
    constexpr int NIT = Kd / 16;

    extern __shared__ __align__(16) __half dynsm[];
    uint32_t uA = smem_u32(dynsm);                 // A: 4 buffers
    uint32_t uB = uA + 4 * BUFH * 2;               // B: 2 buffers

    int tid = threadIdx.x, lane = tid & 31, wid = tid >> 5;
    int e = blockIdx.z;
    int m0 = blockIdx.y * 128;
    int jx = blockIdx.x;
    int base = 0, cnt = 1 << 30;
    if (MODE == 1 || MODE == 2) {
        base = g_off[e];
        cnt = g_off[e + 1] - base;
        if (m0 >= cnt) return;
    }

    // ---- A loader: thread -> (row = tid>>1, half-chunk = tid&1), 16B cp.async
    int arow = tid >> 1, ahalf = tid & 1;
    const __half* asrc;
    {
        long ai;
        if (MODE == 1)      { int s = base + imin(m0 + arow, cnt - 1); ai = (long)g_slot_tok[s] * 1024; }
        else if (MODE == 2) { int s = base + imin(m0 + arow, cnt - 1); ai = (long)s * 512; }
        else                  ai = (long)(m0 + arow) * Kd;
        asrc = A + ai + ahalf * 8;
    }
    uint32_t adst[4];
    #pragma unroll
    for (int b = 0; b < 4; b++)
        adst[b] = uA + (uint32_t)(b * BUFH * 2 + (arow * RS + ahalf * 8) * 2);

    // ---- B loader: thread -> rows r0, r0+64; k quad q (floats)
    int r0 = tid >> 2, q = (tid & 3) * 4;
    const float* bptr[2];
    #pragma unroll
    for (int h = 0; h < 2; h++) {
        int r = r0 + h * 64;
        const float* p;
        if (MODE == 0) {
            int col = jx * 64 + (r >> 1);
            p = ((r & 1) ? B2 : B1) + (long)col * 1024;
        } else if (MODE == 1) {
            int col = jx * 64 + (r >> 1);
            int row = (r & 1) ? (512 + col) : col;
            p = B1 + ((long)e << 20) + (long)row * 1024;
        } else if (MODE == 2) {
            p = B1 + (long)e * (1024 * 512) + (long)(jx * 128 + r) * 512;
        } else {
            p = B1 + (long)(jx * 128 + r) * 512;
        }
        bptr[h] = p + q;
    }

    // ---- ldmatrix lane offsets (within one buffer)
    int wm = wid >> 1, wn = wid & 1;
    int m0w = wm * 32, n0w = wn * 64;
    uint32_t offA[2], offB[4];
    #pragma unroll
    for (int mt = 0; mt < 2; mt++) {
        int row = m0w + mt * 16 + ((lane >> 3) & 1) * 8 + (lane & 7);
        int col = ((lane >> 4) & 1) * 8;
        offA[mt] = (uint32_t)((row * RS + col) * 2);
    }
    #pragma unroll
    for (int nb = 0; nb < 4; nb++) {
        int row = n0w + nb * 16 + ((lane >> 4) & 1) * 8 + (lane & 7);
        int col = ((lane >> 3) & 1) * 8;
        offB[nb] = (uint32_t)((row * RS + col) * 2);
    }

    float acc[2][8][4] = {};

    // ---- prologue: A groups 0,1; B tile 0 staged in regs
    cpa16h(adst[0], asrc);
    cpcommit();
    if (NIT > 1) { cpa16h(adst[1], asrc + 16); cpcommit(); }
    float4 sb[2];
    #pragma unroll
    for (int h = 0; h < 2; h++) sb[h] = *(const float4*)bptr[h];

    for (int it = 0; it < NIT; it++) {
        int pb = it & 1, ab = it & 3;
        // STS B (this iter), from staged regs
        #pragma unroll
        for (int h = 0; h < 2; h++) {
            int r = r0 + h * 64;
            *(uint2*)(dynsm + 4 * BUFH + pb * BUFH + r * RS + q) = cvt4(sb[h]);
        }
        // prefetch next B into regs
        if (it + 1 < NIT) {
            int k0 = (it + 1) * 16;
            #pragma unroll
            for (int h = 0; h < 2; h++) sb[h] = *(const float4*)(bptr[h] + k0);
        }
        // issue A group it+2 (buffer (it+2)&3: last read at it-2, safe)
        if (it + 2 < NIT) {
            cpa16h(adst[(it + 2) & 3], asrc + (it + 2) * 16);
            cpcommit();
        }
        // complete group it
        if (it + 2 < NIT)      asm volatile("cp.async.wait_group 2;" ::: "memory");
        else if (it + 1 < NIT) asm volatile("cp.async.wait_group 1;" ::: "memory");
        else                   asm volatile("cp.async.wait_group 0;" ::: "memory");
        __syncthreads();

        uint32_t aBase = uA + (uint32_t)(ab * BUFH * 2);
        uint32_t bBase = uB + (uint32_t)(pb * BUFH * 2);
        uint32_t ah[2][4];
        #pragma unroll
        for (int mt = 0; mt < 2; mt++)
            ldsm4(ah[mt][0], ah[mt][1], ah[mt][2], ah[mt][3], aBase + offA[mt]);
        #pragma unroll
        for (int nb = 0; nb < 4; nb++) {
            uint32_t bh0, bh1, bh2, bh3;
            ldsm4(bh0, bh1, bh2, bh3, bBase + offB[nb]);
            #pragma unroll
            for (int mt = 0; mt < 2; mt++) {
                mma16(acc[mt][nb * 2],     ah[mt], bh0, bh1);
                mma16(acc[mt][nb * 2 + 1], ah[mt], bh2, bh3);
            }
        }
    }

    // ---- epilogue (lane g rows g,g+8; cols 2tg,2tg+1)
    int g = lane >> 2, tg = lane & 3;
    if (MODE == 0 || MODE == 1) {
        __half* Ch = (__half*)Cv;
        #pragma unroll
        for (int mt = 0; mt < 2; mt++) {
            #pragma unroll
            for (int half = 0; half < 2; half++) {
                int mr = m0 + m0w + mt * 16 + g + half * 8;
                bool v = (MODE == 0) ? true : (mr < cnt);
                if (v) {
                    long orow = (MODE == 0) ? (long)mr : (long)(base + mr);
                    __half* o = Ch + orow * 512 + jx * 64 + (n0w >> 1) + tg;
                    #pragma unroll
                    for (int nt = 0; nt < 8; nt++) {
                        float gg = acc[mt][nt][half * 2];
                        float uu = acc[mt][nt][half * 2 + 1];
                        o[nt * 4] = __float2half_rn((gg / (1.f + expf(-gg))) * uu);
                    }
                }
            }
        }
    } else if (MODE == 2) {
        float* Cf = (float*)Cv;
        #pragma unroll
        for (int mt = 0; mt < 2; mt++) {
            #pragma unroll
            for (int half = 0; half < 2; half++) {
                int mr = m0 + m0w + mt * 16 + g + half * 8;
                if (mr < cnt) {
                    int s = base + mr;
                    float* o = Cf + (long)s * 1024 + jx * 128 + n0w + 2 * tg;
                    #pragma unroll
                    for (int nt = 0; nt < 8; nt++) {
                        o[nt * 8]     = acc[mt][nt][half * 2];
                        o[nt * 8 + 1] = acc[mt][nt][half * 2 + 1];
                    }
                }
            }
        }
    } else {
        float* Cf = (float*)Cv;
        #pragma unroll
        for (int mt = 0; mt < 2; mt++) {
            #pragma unroll
            for (int half = 0; half < 2; half++) {
                int mr = m0 + m0w + mt * 16 + g + half * 8;
                float sg = g_shgate[mr];
                float* o = Cf + (long)mr * 1024 + jx * 128 + n0w + 2 * tg;
                #pragma unroll
                for (int nt = 0; nt < 8; nt++) {
                    o[nt * 8]     = sg * acc[mt][nt][half * 2];
                    o[nt * 8 + 1] = sg * acc[mt][nt][half * 2 + 1];
                }
            }
        }
    }
}

// ---------------- launch ----------------
extern "C" void kernel_launch(void* const* d_in, const int* in_sizes, int n_in,
                              void* d_out, int out_size) {
    const float* x       = (const float*)d_in[0];  // [4096,1024]
    const float* rw      = (const float*)d_in[1];  // [64,1024]
    const float* gate_up = (const float*)d_in[2];  // [64,1024,1024]
    const float* down    = (const float*)d_in[3];  // [64,1024,512]
    const float* shg     = (const float*)d_in[4];  // [512,1024]
    const float* shu     = (const float*)d_in[5];  // [512,1024]
    const float* shd     = (const float*)d_in[6];  // [1024,512]
    const float* sheg    = (const float*)d_in[7];  // [1,1024]

    float* out = (float*)d_out;
    float* probs = nullptr;
    if (out_size >= (int)(TTOK * DHID + TTOK * NEXP))
        probs = out + (size_t)TTOK * DHID;

    float *p_logits, *p_y;
    __half *p_xh, *p_act, *p_acts;
    cudaGetSymbolAddress((void**)&p_logits, g_logits);
    cudaGetSymbolAddress((void**)&p_y, g_y);
    cudaGetSymbolAddress((void**)&p_xh, g_xh);
    cudaGetSymbolAddress((void**)&p_act, g_act);
    cudaGetSymbolAddress((void**)&p_acts, g_acts);

    const int DYN = 6 * BUFH * 2;  // 36864 bytes: 4 A buffers + 2 B buffers
    cudaFuncSetAttribute(mma_gemm<0>, cudaFuncAttributeMaxDynamicSharedMemorySize, DYN);
    cudaFuncSetAttribute(mma_gemm<1>, cudaFuncAttributeMaxDynamicSharedMemorySize, DYN);
    cudaFuncSetAttribute(mma_gemm<2>, cudaFuncAttributeMaxDynamicSharedMemorySize, DYN);
    cudaFuncSetAttribute(mma_gemm<3>, cudaFuncAttributeMaxDynamicSharedMemorySize, DYN);

    // 0) x -> fp16 (one-time rounding; identical to what loaders did before)
    cvt_x_kernel<<<TTOK * DHID / 4 / 256, 256>>>(x);
    // 1) router logits (fp32 SIMT — top-k selection is precision-critical)
    logits_gemm<<<dim3(1, TTOK / 32), 256>>>(x, rw, p_logits);
    // 2) softmax + top2 + shared-expert gate
    softmax_topk_kernel<<<TTOK / 8, 256>>>(x, sheg, probs);
    // 3) dispatch: histogram + scan + slot assignment
    dispatch_kernel<<<1, 1024>>>();
    // 4) shared gate/up + fused swiglu -> g_acts (fp16)
    mma_gemm<0><<<dim3(8, TTOK / 128), 256, DYN>>>(p_xh, shg, shu, p_acts);
    // 5) routed gate_up + fused swiglu -> g_act (fp16)
    mma_gemm<1><<<dim3(8, 2, NEXP), 256, DYN>>>(p_xh, gate_up, nullptr, p_act);
    // 6) shared down + sigmoid-gate -> out (fp32, full overwrite)
    mma_gemm<3><<<dim3(8, TTOK / 128), 256, DYN>>>(p_acts, shd, nullptr, out);
    // 7) routed down -> g_y (fp32 plain stores)
    mma_gemm<2><<<dim3(8, 2, NEXP), 256, DYN>>>(p_act, down, nullptr, p_y);
    // 8) combine: out += w0*y[s0] + w1*y[s1]
    combine_kernel<<<TTOK / 8, 256>>>(out);
}

// round 12
// speedup vs baseline: 1.0857x; 1.0857x over previous
#include <cuda_runtime.h>
#include <cuda_fp16.h>
#include <math.h>
#include <stdint.h>

#define TTOK 4096
#define DHID 1024
#define NEXP 64
#define IMOE 512
#define NPAIR 8192

// ---------------- scratch (static device globals) ----------------
__device__ int    g_off[NEXP + 1];
__device__ int    g_pe[NPAIR];
__device__ float  g_pw[NPAIR];
__device__ int    g_slot_tok[NPAIR];
__device__ int    g_pair_slot[NPAIR];
__device__ float  g_shgate[TTOK];
__device__ float  g_logits[TTOK * NEXP];
__device__ __half g_xh[TTOK * DHID];          // x in fp16         [4096,1024]
__device__ __half g_act[NPAIR * IMOE];        // routed activated  [8192,512] fp16
__device__ __half g_acts[TTOK * IMOE];        // shared activated  [4096,512] fp16
__device__ float  g_y[NPAIR * DHID];          // routed down out   [8192,1024]

// ---------------- helpers ----------------
__device__ __forceinline__ uint32_t smem_u32(const void* p) {
    uint32_t a;
    asm("{ .reg .u64 t; cvta.to.shared.u64 t, %1; cvt.u32.u64 %0, t; }" : "=r"(a) : "l"(p));
    return a;
}
__device__ __forceinline__ void ldsm4(uint32_t& d0, uint32_t& d1, uint32_t& d2, uint32_t& d3,
                                      uint32_t a) {
    asm volatile("ldmatrix.sync.aligned.m8n8.x4.shared.b16 {%0,%1,%2,%3}, [%4];"
                 : "=r"(d0), "=r"(d1), "=r"(d2), "=r"(d3) : "r"(a));
}
// D += A(m16k16 f16) * B(k16n8 f16), fp32 acc
__device__ __forceinline__ void mma16(float* c, const uint32_t* a, uint32_t b0, uint32_t b1) {
    asm volatile(
        "mma.sync.aligned.m16n8k16.row.col.f32.f16.f16.f32 "
        "{%0,%1,%2,%3}, {%4,%5,%6,%7}, {%8,%9}, {%0,%1,%2,%3};"
        : "+f"(c[0]), "+f"(c[1]), "+f"(c[2]), "+f"(c[3])
        : "r"(a[0]), "r"(a[1]), "r"(a[2]), "r"(a[3]), "r"(b0), "r"(b1));
}
__device__ __forceinline__ uint32_t h2u(__half2 h) {
    uint32_t u;
    memcpy(&u, &h, 4);
    return u;
}
__device__ __forceinline__ uint2 cvt4(float4 v) {
    __half2 h01 = __floats2half2_rn(v.x, v.y);
    __half2 h23 = __floats2half2_rn(v.z, v.w);
    return make_uint2(h2u(h01), h2u(h23));
}
__device__ __forceinline__ int imin(int a, int b) { return a < b ? a : b; }

// ---------------- pre/post kernels ----------------
__global__ void cvt_x_kernel(const float* __restrict__ x) {
    int i = blockIdx.x * 256 + threadIdx.x;      // index of float4 group
    float4 v = ((const float4*)x)[i];
    *(uint2*)&g_xh[(size_t)i * 4] = cvt4(v);
}

__global__ void softmax_topk_kernel(const float* __restrict__ x,
                                    const float* __restrict__ sheg,
                                    float* __restrict__ probs_out) {
    int w = threadIdx.x >> 5, lane = threadIdx.x & 31;
    int t = blockIdx.x * 8 + w;
    if (t >= TTOK) return;

    const float* xr = x + (size_t)t * DHID;
    float sd = 0.f;
    for (int k = lane; k < DHID; k += 32) sd += xr[k] * sheg[k];
    #pragma unroll
    for (int o = 16; o; o >>= 1) sd += __shfl_xor_sync(~0u, sd, o);
    if (lane == 0) g_shgate[t] = 1.f / (1.f + expf(-sd));

    float l0 = g_logits[t * 64 + lane];
    float l1 = g_logits[t * 64 + 32 + lane];
    float m = fmaxf(l0, l1);
    #pragma unroll
    for (int o = 16; o; o >>= 1) m = fmaxf(m, __shfl_xor_sync(~0u, m, o));
    float e0 = expf(l0 - m), e1 = expf(l1 - m);
    float s = e0 + e1;
    #pragma unroll
    for (int o = 16; o; o >>= 1) s += __shfl_xor_sync(~0u, s, o);
    float inv = 1.f / s;
    float p0 = e0 * inv, p1 = e1 * inv;
    if (probs_out) {
        probs_out[t * 64 + lane]      = p0;
        probs_out[t * 64 + 32 + lane] = p1;
    }
    float v0, v1; int i0, i1;
    if (p1 > p0) { v0 = p1; i0 = lane + 32; v1 = p0; i1 = lane; }
    else         { v0 = p0; i0 = lane;      v1 = p1; i1 = lane + 32; }
    #pragma unroll
    for (int o = 16; o; o >>= 1) {
        float w0 = __shfl_xor_sync(~0u, v0, o); int j0 = __shfl_xor_sync(~0u, i0, o);
        float w1 = __shfl_xor_sync(~0u, v1, o); int j1 = __shfl_xor_sync(~0u, i1, o);
        if (w0 > v0 || (w0 == v0 && j0 < i0)) { v1 = v0; i1 = i0; v0 = w0; i0 = j0;
            if (w1 > v1 || (w1 == v1 && j1 < i1)) { v1 = w1; i1 = j1; } }
        else if (w0 > v1 || (w0 == v1 && j0 < i1)) { v1 = w0; i1 = j0; }
    }
    if (lane == 0) {
        float inv2 = 1.f / (v0 + v1 + 1e-9f);
        int p = t * 2;
        g_pe[p] = i0;     g_pw[p] = v0 * inv2;
        g_pe[p + 1] = i1; g_pw[p + 1] = v1 * inv2;
    }
}

// single-block dispatch: histogram -> scan -> scatter slots
__global__ void dispatch_kernel() {
    __shared__ int cnt[NEXP];
    __shared__ int off[NEXP + 1];
    __shared__ int fill[NEXP];
    int tid = threadIdx.x;
    if (tid < NEXP) cnt[tid] = 0;
    __syncthreads();
    for (int p = tid; p < NPAIR; p += 1024) atomicAdd(&cnt[g_pe[p]], 1);
    __syncthreads();
    if (tid == 0) {
        int a = 0;
        for (int e = 0; e < NEXP; e++) { off[e] = a; fill[e] = a; a += cnt[e]; }
        off[NEXP] = a;
    }
    __syncthreads();
    if (tid <= NEXP) g_off[tid] = off[tid];
    for (int p = tid; p < NPAIR; p += 1024) {
        int s = atomicAdd(&fill[g_pe[p]], 1);
        g_slot_tok[s] = p >> 1;
        g_pair_slot[p] = s;
    }
}

// final combine: out[t] += w0*y[slot0] + w1*y[slot1]
__global__ void combine_kernel(float* __restrict__ out) {
    int w = threadIdx.x >> 5, lane = threadIdx.x & 31;
    int t = blockIdx.x * 8 + w;
    if (t >= TTOK) return;
    int s0 = g_pair_slot[2 * t], s1 = g_pair_slot[2 * t + 1];
    float w0 = g_pw[2 * t], w1 = g_pw[2 * t + 1];
    float4* o = (float4*)(out + (long)t * DHID);
    const float4* y0 = (const float4*)(g_y + (long)s0 * DHID);
    const float4* y1 = (const float4*)(g_y + (long)s1 * DHID);
    for (int i = lane; i < DHID / 4; i += 32) {
        float4 a = o[i], b = y0[i], c = y1[i];
        a.x += w0 * b.x + w1 * c.x;
        a.y += w0 * b.y + w1 * c.y;
        a.z += w0 * b.z + w1 * c.z;
        a.w += w0 * b.w + w1 * c.w;
        o[i] = a;
    }
}

// -------- fp32 SIMT GEMM for router logits (precision-critical) --------
__global__ void __launch_bounds__(256)
logits_gemm(const float* __restrict__ A, const float* __restrict__ B,
            float* __restrict__ C) {
    const int N = 64, Kd = 1024;
    __shared__ float As[32][33];
    __shared__ float Bs[32][65];
    int tid = threadIdx.x;
    int m0 = blockIdx.y * 32;
    int tx = tid & 15, ty = tid >> 4;

    int ar = tid >> 3, akc = (tid & 7) * 4;
    const float* Arow = A + (long)(m0 + ar) * Kd + akc;
    int br0 = tid >> 3;
    int bkc = (tid & 7) * 4;
    const float* Brow0 = B + (long)br0 * Kd + bkc;
    const float* Brow1 = B + (long)(br0 + 32) * Kd + bkc;

    float acc[2][4] = {};
    for (int k0 = 0; k0 < Kd; k0 += 32) {
        float4 av = *(const float4*)(Arow + k0);
        float4 bv0 = *(const float4*)(Brow0 + k0);
        float4 bv1 = *(const float4*)(Brow1 + k0);
        As[akc + 0][ar] = av.x; As[akc + 1][ar] = av.y;
        As[akc + 2][ar] = av.z; As[akc + 3][ar] = av.w;
        Bs[bkc + 0][br0] = bv0.x; Bs[bkc + 1][br0] = bv0.y;
        Bs[bkc + 2][br0] = bv0.z; Bs[bkc + 3][br0] = bv0.w;
        Bs[bkc + 0][br0 + 32] = bv1.x; Bs[bkc + 1][br0 + 32] = bv1.y;
        Bs[bkc + 2][br0 + 32] = bv1.z; Bs[bkc + 3][br0 + 32] = bv1.w;
        __syncthreads();
        #pragma unroll 8
        for (int kk = 0; kk < 32; kk++) {
            float a0 = As[kk][ty * 2], a1 = As[kk][ty * 2 + 1];
            #pragma unroll
            for (int j = 0; j < 4; j++) {
                float b = Bs[kk][tx * 4 + j];
                acc[0][j] += a0 * b;
                acc[1][j] += a1 * b;
            }
        }
        __syncthreads();
    }
    #pragma unroll
    for (int i = 0; i < 2; i++)
        #pragma unroll
        for (int j = 0; j < 4; j++)
            C[(long)(m0 + ty * 2 + i) * N + tx * 4 + j] = acc[i][j];
}

// ------- fp16 mma.sync GEMM, CTA 128x128, warp 32x64, BK=16 -------
// R9 pipeline (LDG -> reg stage -> STS, double buffer, one sync per iter).
// A source is fp16 in gmem: LDG.64, no cvt. B is fp32 weights: LDG.128 + cvt.
// MODE 0: shared gate/up fused (A=g_xh; B even=shg, odd=shu) -> g_acts (fp16)
// MODE 1: routed gate/up fused (A=g_xh via g_slot_tok; B=gate_up[e]) -> g_act (fp16)
// MODE 2: routed down (A=g_act slots, K=512; B=down[e]) -> g_y (fp32)
// MODE 3: shared down (A=g_acts, K=512; B=shd) -> out = shgate*v (fp32)
#define RS 24              // smem row stride in halves (48B)
#define TILEH (128 * RS)   // halves per tile buffer

template <int MODE>
__global__ void __launch_bounds__(256, 2)
mma_gemm(const __half* __restrict__ A, const float* __restrict__ B1,
         const float* __restrict__ B2, void* __restrict__ Cv) {
    constexpr int Kd  = (MODE == 0 || MODE == 1) ? 1024 : 512;
    constexpr int NIT = Kd / 16;

    extern __shared__ __align__(16) __half dynsm[];
    __half* pAh = dynsm;                 // [2][128][RS]
    __half* pBh = dynsm + 2 * TILEH;

    int tid = threadIdx.x, lane = tid & 31, wid = tid >> 5;
    int e = blockIdx.z;
    int m0 = blockIdx.y * 128;
    int jx = blockIdx.x;
    int base = 0, cnt = 1 << 30;
    if (MODE == 1 || MODE == 2) {
        base = g_off[e];
        cnt = g_off[e + 1] - base;
        if (m0 >= cnt) return;
    }

    // ---- loader: thread handles rows r0, r0+64; k quad q (4 elements)
    int r0 = tid >> 2, q = (tid & 3) * 4;
    const __half* aptr[2];
    const float* bptr[2];
    #pragma unroll
    for (int h = 0; h < 2; h++) {
        int r = r0 + h * 64;
        long ai;
        if (MODE == 1)      { int s = base + imin(m0 + r, cnt - 1); ai = (long)g_slot_tok[s] * 1024; }
        else if (MODE == 2) { int s = base + imin(m0 + r, cnt - 1); ai = (long)s * 512; }
        else                  ai = (long)(m0 + r) * Kd;
        aptr[h] = A + ai + q;

        const float* p;
        if (MODE == 0) {
            int col = jx * 64 + (r >> 1);
            p = ((r & 1) ? B2 : B1) + (long)col * 1024;
        } else if (MODE == 1) {
            int col = jx * 64 + (r >> 1);
            int row = (r & 1) ? (512 + col) : col;
            p = B1 + ((long)e << 20) + (long)row * 1024;
        } else if (MODE == 2) {
            p = B1 + (long)e * (1024 * 512) + (long)(jx * 128 + r) * 512;
        } else {
            p = B1 + (long)(jx * 128 + r) * 512;
        }
        bptr[h] = p + q;
    }

    // ---- ldmatrix lane offsets (bytes within a tile buffer)
    int wm = wid >> 1, wn = wid & 1;
    int m0w = wm * 32, n0w = wn * 64;
    uint32_t offA[2], offB[4];
    #pragma unroll
    for (int mt = 0; mt < 2; mt++) {
        int row = m0w + mt * 16 + ((lane >> 3) & 1) * 8 + (lane & 7);
        int col = ((lane >> 4) & 1) * 8;
        offA[mt] = (uint32_t)((row * RS + col) * 2);
    }
    #pragma unroll
    for (int nb = 0; nb < 4; nb++) {
        int row = n0w + nb * 16 + ((lane >> 4) & 1) * 8 + (lane & 7);
        int col = ((lane >> 3) & 1) * 8;
        offB[nb] = (uint32_t)((row * RS + col) * 2);
    }
    uint32_t uAh = smem_u32(pAh), uBh = smem_u32(pBh);

    float acc[2][8][4] = {};

    // prologue: stage tile 0 in registers
    uint2 sa[2];
    float4 sb[2];
    #pragma unroll
    for (int h = 0; h < 2; h++) {
        sa[h] = *(const uint2*)aptr[h];
        sb[h] = *(const float4*)bptr[h];
    }

    for (int it = 0; it < NIT; it++) {
        int p = it & 1;
        // STS current staged tile (A: direct fp16; B: cvt)
        #pragma unroll
        for (int h = 0; h < 2; h++) {
            int r = r0 + h * 64;
            *(uint2*)&pAh[p * TILEH + r * RS + q] = sa[h];
            *(uint2*)&pBh[p * TILEH + r * RS + q] = cvt4(sb[h]);
        }
        // prefetch next tile into registers (hidden by this iter's compute)
        if (it + 1 < NIT) {
            int k0 = (it + 1) * 16;
            #pragma unroll
            for (int h = 0; h < 2; h++) {
                sa[h] = *(const uint2*)(aptr[h] + k0);
                sb[h] = *(const float4*)(bptr[h] + k0);
            }
        }
        __syncthreads();

        uint32_t bufo = (uint32_t)(p * TILEH * 2);
        uint32_t ah[2][4];
        #pragma unroll
        for (int mt = 0; mt < 2; mt++)
            ldsm4(ah[mt][0], ah[mt][1], ah[mt][2], ah[mt][3], uAh + bufo + offA[mt]);
        #pragma unroll
        for (int nb = 0; nb < 4; nb++) {
            uint32_t bh0, bh1, bh2, bh3;
            ldsm4(bh0, bh1, bh2, bh3, uBh + bufo + offB[nb]);
            #pragma unroll
            for (int mt = 0; mt < 2; mt++) {
                mma16(acc[mt][nb * 2],     ah[mt], bh0, bh1);
                mma16(acc[mt][nb * 2 + 1], ah[mt], bh2, bh3);
            }
        }
    }

    // ---- epilogue (lane g=lane>>2, tg=lane&3; rows g,g+8; cols 2tg,2tg+1)
    int g = lane >> 2, tg = lane & 3;
    if (MODE == 0 || MODE == 1) {
        __half* Ch = (__half*)Cv;
        #pragma unroll
        for (int mt = 0; mt < 2; mt++) {
            #pragma unroll
            for (int half = 0; half < 2; half++) {
                int mr = m0 + m0w + mt * 16 + g + half * 8;
                bool v = (MODE == 0) ? true : (mr < cnt);
                if (v) {
                    long orow = (MODE == 0) ? (long)mr : (long)(base + mr);
                    __half* o = Ch + orow * 512 + jx * 64 + (n0w >> 1) + tg;
                    #pragma unroll
                    for (int nt = 0; nt < 8; nt++) {
                        float gg = acc[mt][nt][half * 2];
                        float uu = acc[mt][nt][half * 2 + 1];
                        o[nt * 4] = __float2half_rn((gg / (1.f + expf(-gg))) * uu);
                    }
                }
            }
        }
    } else if (MODE == 2) {
        float* Cf = (float*)Cv;
        #pragma unroll
        for (int mt = 0; mt < 2; mt++) {
            #pragma unroll
            for (int half = 0; half < 2; half++) {
                int mr = m0 + m0w + mt * 16 + g + half * 8;
                if (mr < cnt) {
                    int s = base + mr;
                    float* o = Cf + (long)s * 1024 + jx * 128 + n0w + 2 * tg;
                    #pragma unroll
                    for (int nt = 0; nt < 8; nt++) {
                        o[nt * 8]     = acc[mt][nt][half * 2];
                        o[nt * 8 + 1] = acc[mt][nt][half * 2 + 1];
                    }
                }
            }
        }
    } else {
        float* Cf = (float*)Cv;
        #pragma unroll
        for (int mt = 0; mt < 2; mt++) {
            #pragma unroll
            for (int half = 0; half < 2; half++) {
                int mr = m0 + m0w + mt * 16 + g + half * 8;
                float sg = g_shgate[mr];
                float* o = Cf + (long)mr * 1024 + jx * 128 + n0w + 2 * tg;
                #pragma unroll
                for (int nt = 0; nt < 8; nt++) {
                    o[nt * 8]     = sg * acc[mt][nt][half * 2];
                    o[nt * 8 + 1] = sg * acc[mt][nt][half * 2 + 1];
                }
            }
        }
    }
}

// ---------------- launch ----------------
extern "C" void kernel_launch(void* const* d_in, const int* in_sizes, int n_in,
                              void* d_out, int out_size) {
    const float* x       = (const float*)d_in[0];  // [4096,1024]
    const float* rw      = (const float*)d_in[1];  // [64,1024]
    const float* gate_up = (const float*)d_in[2];  // [64,1024,1024]
    const float* down    = (const float*)d_in[3];  // [64,1024,512]
    const float* shg     = (const float*)d_in[4];  // [512,1024]
    const float* shu     = (const float*)d_in[5];  // [512,1024]
    const float* shd     = (const float*)d_in[6];  // [1024,512]
    const float* sheg    = (const float*)d_in[7];  // [1,1024]

    float* out = (float*)d_out;
    float* probs = nullptr;
    if (out_size >= (int)(TTOK * DHID + TTOK * NEXP))
        probs = out + (size_t)TTOK * DHID;

    float *p_logits, *p_y;
    __half *p_xh, *p_act, *p_acts;
    cudaGetSymbolAddress((void**)&p_logits, g_logits);
    cudaGetSymbolAddress((void**)&p_y, g_y);
    cudaGetSymbolAddress((void**)&p_xh, g_xh);
    cudaGetSymbolAddress((void**)&p_act, g_act);
    cudaGetSymbolAddress((void**)&p_acts, g_acts);

    const int DYN = 4 * TILEH * 2;  // 24576 bytes (A + B, double-buffered)
    cudaFuncSetAttribute(mma_gemm<0>, cudaFuncAttributeMaxDynamicSharedMemorySize, DYN);
    cudaFuncSetAttribute(mma_gemm<1>, cudaFuncAttributeMaxDynamicSharedMemorySize, DYN);
    cudaFuncSetAttribute(mma_gemm<2>, cudaFuncAttributeMaxDynamicSharedMemorySize, DYN);
    cudaFuncSetAttribute(mma_gemm<3>, cudaFuncAttributeMaxDynamicSharedMemorySize, DYN);

    // 0) x -> fp16 (one-time rounding; identical to what loaders did before)
    cvt_x_kernel<<<TTOK * DHID / 4 / 256, 256>>>(x);
    // 1) router logits (fp32 SIMT — top-k selection is precision-critical)
    logits_gemm<<<dim3(1, TTOK / 32), 256>>>(x, rw, p_logits);
    // 2) softmax + top2 + shared-expert gate
    softmax_topk_kernel<<<TTOK / 8, 256>>>(x, sheg, probs);
    // 3) dispatch: histogram + scan + slot assignment
    dispatch_kernel<<<1, 1024>>>();
    // 4) shared gate/up + fused swiglu -> g_acts (fp16)
    mma_gemm<0><<<dim3(8, TTOK / 128), 256, DYN>>>(p_xh, shg, shu, p_acts);
    // 5) routed gate_up + fused swiglu -> g_act (fp16)
    mma_gemm<1><<<dim3(8, 2, NEXP), 256, DYN>>>(p_xh, gate_up, nullptr, p_act);
    // 6) shared down + sigmoid-gate -> out (fp32, full overwrite)
    mma_gemm<3><<<dim3(8, TTOK / 128), 256, DYN>>>(p_acts, shd, nullptr, out);
    // 7) routed down -> g_y (fp32 plain stores)
    mma_gemm<2><<<dim3(8, 2, NEXP), 256, DYN>>>(p_act, down, nullptr, p_y);
    // 8) combine: out += w0*y[s0] + w1*y[s1]
    combine_kernel<<<TTOK / 8, 256>>>(out);
}

// round 13
// speedup vs baseline: 1.1067x; 1.0194x over previous
#include <cuda_runtime.h>
#include <cuda_fp16.h>
#include <math.h>
#include <stdint.h>

#define TTOK 4096
#define DHID 1024
#define NEXP 64
#define IMOE 512
#define NPAIR 8192

// ---------------- scratch (static device globals) ----------------
__device__ int    g_off[NEXP + 1];
__device__ int    g_pe[NPAIR];
__device__ float  g_pw[NPAIR];
__device__ int    g_slot_tok[NPAIR];
__device__ int    g_pair_slot[NPAIR];
__device__ float  g_shgate[TTOK];
__device__ float  g_logits[TTOK * NEXP];
__device__ __half g_act[NPAIR * IMOE];        // routed activated  [8192,512] fp16
__device__ __half g_acts[TTOK * IMOE];        // shared activated  [4096,512] fp16
__device__ float  g_y[NPAIR * DHID];          // routed down out   [8192,1024]

// ---------------- helpers ----------------
__device__ __forceinline__ uint32_t smem_u32(const void* p) {
    uint32_t a;
    asm("{ .reg .u64 t; cvta.to.shared.u64 t, %1; cvt.u32.u64 %0, t; }" : "=r"(a) : "l"(p));
    return a;
}
__device__ __forceinline__ void ldsm4(uint32_t& d0, uint32_t& d1, uint32_t& d2, uint32_t& d3,
                                      uint32_t a) {
    asm volatile("ldmatrix.sync.aligned.m8n8.x4.shared.b16 {%0,%1,%2,%3}, [%4];"
                 : "=r"(d0), "=r"(d1), "=r"(d2), "=r"(d3) : "r"(a));
}
// D += A(m16k16 f16) * B(k16n8 f16), fp32 acc
__device__ __forceinline__ void mma16(float* c, const uint32_t* a, uint32_t b0, uint32_t b1) {
    asm volatile(
        "mma.sync.aligned.m16n8k16.row.col.f32.f16.f16.f32 "
        "{%0,%1,%2,%3}, {%4,%5,%6,%7}, {%8,%9}, {%0,%1,%2,%3};"
        : "+f"(c[0]), "+f"(c[1]), "+f"(c[2]), "+f"(c[3])
        : "r"(a[0]), "r"(a[1]), "r"(a[2]), "r"(a[3]), "r"(b0), "r"(b1));
}
__device__ __forceinline__ uint32_t h2u(__half2 h) {
    uint32_t u;
    memcpy(&u, &h, 4);
    return u;
}
__device__ __forceinline__ uint2 cvt4(float4 v) {
    __half2 h01 = __floats2half2_rn(v.x, v.y);
    __half2 h23 = __floats2half2_rn(v.z, v.w);
    return make_uint2(h2u(h01), h2u(h23));
}
__device__ __forceinline__ int imin(int a, int b) { return a < b ? a : b; }

// ---------------- routing kernels ----------------
__global__ void softmax_topk_kernel(const float* __restrict__ x,
                                    const float* __restrict__ sheg,
                                    float* __restrict__ probs_out) {
    int w = threadIdx.x >> 5, lane = threadIdx.x & 31;
    int t = blockIdx.x * 8 + w;
    if (t >= TTOK) return;

    const float* xr = x + (size_t)t * DHID;
    float sd = 0.f;
    for (int k = lane; k < DHID; k += 32) sd += xr[k] * sheg[k];
    #pragma unroll
    for (int o = 16; o; o >>= 1) sd += __shfl_xor_sync(~0u, sd, o);
    if (lane == 0) g_shgate[t] = 1.f / (1.f + expf(-sd));

    float l0 = g_logits[t * 64 + lane];
    float l1 = g_logits[t * 64 + 32 + lane];
    float m = fmaxf(l0, l1);
    #pragma unroll
    for (int o = 16; o; o >>= 1) m = fmaxf(m, __shfl_xor_sync(~0u, m, o));
    float e0 = expf(l0 - m), e1 = expf(l1 - m);
    float s = e0 + e1;
    #pragma unroll
    for (int o = 16; o; o >>= 1) s += __shfl_xor_sync(~0u, s, o);
    float inv = 1.f / s;
    float p0 = e0 * inv, p1 = e1 * inv;
    if (probs_out) {
        probs_out[t * 64 + lane]      = p0;
        probs_out[t * 64 + 32 + lane] = p1;
    }
    float v0, v1; int i0, i1;
    if (p1 > p0) { v0 = p1; i0 = lane + 32; v1 = p0; i1 = lane; }
    else         { v0 = p0; i0 = lane;      v1 = p1; i1 = lane + 32; }
    #pragma unroll
    for (int o = 16; o; o >>= 1) {
        float w0 = __shfl_xor_sync(~0u, v0, o); int j0 = __shfl_xor_sync(~0u, i0, o);
        float w1 = __shfl_xor_sync(~0u, v1, o); int j1 = __shfl_xor_sync(~0u, i1, o);
        if (w0 > v0 || (w0 == v0 && j0 < i0)) { v1 = v0; i1 = i0; v0 = w0; i0 = j0;
            if (w1 > v1 || (w1 == v1 && j1 < i1)) { v1 = w1; i1 = j1; } }
        else if (w0 > v1 || (w0 == v1 && j0 < i1)) { v1 = w0; i1 = j0; }
    }
    if (lane == 0) {
        float inv2 = 1.f / (v0 + v1 + 1e-9f);
        int p = t * 2;
        g_pe[p] = i0;     g_pw[p] = v0 * inv2;
        g_pe[p + 1] = i1; g_pw[p + 1] = v1 * inv2;
    }
}

// single-block dispatch: histogram -> scan -> scatter slots
__global__ void dispatch_kernel() {
    __shared__ int cnt[NEXP];
    __shared__ int off[NEXP + 1];
    __shared__ int fill[NEXP];
    int tid = threadIdx.x;
    if (tid < NEXP) cnt[tid] = 0;
    __syncthreads();
    for (int p = tid; p < NPAIR; p += 1024) atomicAdd(&cnt[g_pe[p]], 1);
    __syncthreads();
    if (tid == 0) {
        int a = 0;
        for (int e = 0; e < NEXP; e++) { off[e] = a; fill[e] = a; a += cnt[e]; }
        off[NEXP] = a;
    }
    __syncthreads();
    if (tid <= NEXP) g_off[tid] = off[tid];
    for (int p = tid; p < NPAIR; p += 1024) {
        int s = atomicAdd(&fill[g_pe[p]], 1);
        g_slot_tok[s] = p >> 1;
        g_pair_slot[p] = s;
    }
}

// final combine: out[t] += w0*y[slot0] + w1*y[slot1]
__global__ void combine_kernel(float* __restrict__ out) {
    int w = threadIdx.x >> 5, lane = threadIdx.x & 31;
    int t = blockIdx.x * 8 + w;
    if (t >= TTOK) return;
    int s0 = g_pair_slot[2 * t], s1 = g_pair_slot[2 * t + 1];
    float w0 = g_pw[2 * t], w1 = g_pw[2 * t + 1];
    float4* o = (float4*)(out + (long)t * DHID);
    const float4* y0 = (const float4*)(g_y + (long)s0 * DHID);
    const float4* y1 = (const float4*)(g_y + (long)s1 * DHID);
    for (int i = lane; i < DHID / 4; i += 32) {
        float4 a = o[i], b = y0[i], c = y1[i];
        a.x += w0 * b.x + w1 * c.x;
        a.y += w0 * b.y + w1 * c.y;
        a.z += w0 * b.z + w1 * c.z;
        a.w += w0 * b.w + w1 * c.w;
        o[i] = a;
    }
}

// -------- fp32 SIMT GEMM for router logits (precision-critical) --------
__global__ void __launch_bounds__(256)
logits_gemm(const float* __restrict__ A, const float* __restrict__ B,
            float* __restrict__ C) {
    const int N = 64, Kd = 1024;
    __shared__ float As[32][33];
    __shared__ float Bs[32][65];
    int tid = threadIdx.x;
    int m0 = blockIdx.y * 32;
    int tx = tid & 15, ty = tid >> 4;

    int ar = tid >> 3, akc = (tid & 7) * 4;
    const float* Arow = A + (long)(m0 + ar) * Kd + akc;
    int br0 = tid >> 3;
    int bkc = (tid & 7) * 4;
    const float* Brow0 = B + (long)br0 * Kd + bkc;
    const float* Brow1 = B + (long)(br0 + 32) * Kd + bkc;

    float acc[2][4] = {};
    for (int k0 = 0; k0 < Kd; k0 += 32) {
        float4 av = *(const float4*)(Arow + k0);
        float4 bv0 = *(const float4*)(Brow0 + k0);
        float4 bv1 = *(const float4*)(Brow1 + k0);
        As[akc + 0][ar] = av.x; As[akc + 1][ar] = av.y;
        As[akc + 2][ar] = av.z; As[akc + 3][ar] = av.w;
        Bs[bkc + 0][br0] = bv0.x; Bs[bkc + 1][br0] = bv0.y;
        Bs[bkc + 2][br0] = bv0.z; Bs[bkc + 3][br0] = bv0.w;
        Bs[bkc + 0][br0 + 32] = bv1.x; Bs[bkc + 1][br0 + 32] = bv1.y;
        Bs[bkc + 2][br0 + 32] = bv1.z; Bs[bkc + 3][br0 + 32] = bv1.w;
        __syncthreads();
        #pragma unroll 8
        for (int kk = 0; kk < 32; kk++) {
            float a0 = As[kk][ty * 2], a1 = As[kk][ty * 2 + 1];
            #pragma unroll
            for (int j = 0; j < 4; j++) {
                float b = Bs[kk][tx * 4 + j];
                acc[0][j] += a0 * b;
                acc[1][j] += a1 * b;
            }
        }
        __syncthreads();
    }
    #pragma unroll
    for (int i = 0; i < 2; i++)
        #pragma unroll
        for (int j = 0; j < 4; j++)
            C[(long)(m0 + ty * 2 + i) * N + tx * 4 + j] = acc[i][j];
}

// ------- fp16 mma.sync GEMM, CTA 128x128, warp 32x64, BK=32, XOR-swizzled smem -------
// Layout: tile 128 rows x 32 halves (64B rows, no pad); 16B unit u' = u ^ ((row>>1)&3).
// Conflict-free for STS (8-thread waves cover 8 distinct bank groups) and all
// ldmatrix 8-row wavefronts (evens {u^s} distinct, odds offset by 4 groups).
// MODE 0: shared gate/up fused (A=x fp32; B even=shg, odd=shu) -> g_acts (fp16)
// MODE 1: routed gate/up fused (A=x fp32 via g_slot_tok; B=gate_up[e]) -> g_act (fp16)
// MODE 2: routed down (A=g_act fp16 slots, K=512; B=down[e]) -> g_y (fp32)
// MODE 3: shared down (A=g_acts fp16, K=512; B=shd) -> out = shgate*v (fp32)
#define TILEH2 (128 * 32)   // halves per tile buffer = 8KB

template <int MODE>
__global__ void __launch_bounds__(256, 2)
mma_gemm(const float* __restrict__ A32, const __half* __restrict__ A16,
         const float* __restrict__ B1, const float* __restrict__ B2,
         void* __restrict__ Cv) {
    constexpr bool AF32 = (MODE == 0 || MODE == 1);
    constexpr int Kd  = AF32 ? 1024 : 512;
    constexpr int NIT = Kd / 32;

    extern __shared__ __align__(16) __half dynsm[];
    __half* pA = dynsm;                  // 2 buffers
    __half* pB = dynsm + 2 * TILEH2;     // 2 buffers

    int tid = threadIdx.x, lane = tid & 31, wid = tid >> 5;
    int e = blockIdx.z;
    int m0 = blockIdx.y * 128;
    int jx = blockIdx.x;
    int base = 0, cnt = 1 << 30;
    if (MODE == 1 || MODE == 2) {
        base = g_off[e];
        cnt = g_off[e + 1] - base;
        if (m0 >= cnt) return;
    }

    // ---- loader: thread handles tile rows {r0, r0+64}, 16B unit u (8 elements)
    int r0 = tid >> 2, u = tid & 3;
    const float* af[2];
    const __half* ah16[2];
    const float* bf[2];
    uint32_t stsoff[2];                 // swizzled half-offset within a tile
    #pragma unroll
    for (int h = 0; h < 2; h++) {
        int r = r0 + h * 64;
        long ai;
        if (MODE == 1)      { int s = base + imin(m0 + r, cnt - 1); ai = (long)g_slot_tok[s] * 1024; }
        else if (MODE == 2) { int s = base + imin(m0 + r, cnt - 1); ai = (long)s * 512; }
        else                  ai = (long)(m0 + r) * Kd;
        if (AF32) af[h] = A32 + ai + u * 8;
        else      ah16[h] = A16 + ai + u * 8;

        const float* p;
        if (MODE == 0) {
            int col = jx * 64 + (r >> 1);
            p = ((r & 1) ? B2 : B1) + (long)col * 1024;
        } else if (MODE == 1) {
            int col = jx * 64 + (r >> 1);
            int row = (r & 1) ? (512 + col) : col;
            p = B1 + ((long)e << 20) + (long)row * 1024;
        } else if (MODE == 2) {
            p = B1 + (long)e * (1024 * 512) + (long)(jx * 128 + r) * 512;
        } else {
            p = B1 + (long)(jx * 128 + r) * 512;
        }
        bf[h] = p + u * 8;

        int up = u ^ ((r >> 1) & 3);
        stsoff[h] = (uint32_t)(r * 32 + up * 8);
    }

    // ---- ldmatrix lane byte offsets (ks=0; ks=1 is offset ^ 32)
    int wm = wid >> 1, wn = wid & 1;
    int m0w = wm * 32, n0w = wn * 64;
    uint32_t offA[2], offB[4];
    #pragma unroll
    for (int mt = 0; mt < 2; mt++) {
        int rl = m0w + mt * 16 + ((lane >> 3) & 1) * 8 + (lane & 7);
        int uu = (lane >> 4) & 1;
        int up = uu ^ ((rl >> 1) & 3);
        offA[mt] = (uint32_t)((rl * 32 + up * 8) * 2);
    }
    #pragma unroll
    for (int nb = 0; nb < 4; nb++) {
        int rl = n0w + nb * 16 + ((lane >> 4) & 1) * 8 + (lane & 7);
        int uu = (lane >> 3) & 1;
        int up = uu ^ ((rl >> 1) & 3);
        offB[nb] = (uint32_t)((rl * 32 + up * 8) * 2);
    }
    uint32_t uA = smem_u32(pA), uB = smem_u32(pB);

    float acc[2][8][4] = {};

    // ---- staging (converted to fp16 immediately; 8 regs per side)
    uint4 sa[2], sb[2];
    #pragma unroll
    for (int h = 0; h < 2; h++) {
        if (AF32) {
            float4 f0 = *(const float4*)(af[h]);
            float4 f1 = *(const float4*)(af[h] + 4);
            uint2 c0 = cvt4(f0), c1 = cvt4(f1);
            sa[h] = make_uint4(c0.x, c0.y, c1.x, c1.y);
        } else {
            sa[h] = *(const uint4*)(ah16[h]);
        }
        float4 g0 = *(const float4*)(bf[h]);
        float4 g1 = *(const float4*)(bf[h] + 4);
        uint2 d0 = cvt4(g0), d1 = cvt4(g1);
        sb[h] = make_uint4(d0.x, d0.y, d1.x, d1.y);
    }

    for (int it = 0; it < NIT; it++) {
        int p = it & 1;
        // STS staged tile
        #pragma unroll
        for (int h = 0; h < 2; h++) {
            *(uint4*)&pA[p * TILEH2 + stsoff[h]] = sa[h];
            *(uint4*)&pB[p * TILEH2 + stsoff[h]] = sb[h];
        }
        // prefetch next tile into registers
        if (it + 1 < NIT) {
            int k0 = (it + 1) * 32;
            #pragma unroll
            for (int h = 0; h < 2; h++) {
                if (AF32) {
                    float4 f0 = *(const float4*)(af[h] + k0);
                    float4 f1 = *(const float4*)(af[h] + k0 + 4);
                    uint2 c0 = cvt4(f0), c1 = cvt4(f1);
                    sa[h] = make_uint4(c0.x, c0.y, c1.x, c1.y);
                } else {
                    sa[h] = *(const uint4*)(ah16[h] + k0);
                }
                float4 g0 = *(const float4*)(bf[h] + k0);
                float4 g1 = *(const float4*)(bf[h] + k0 + 4);
                uint2 d0 = cvt4(g0), d1 = cvt4(g1);
                sb[h] = make_uint4(d0.x, d0.y, d1.x, d1.y);
            }
        }
        __syncthreads();

        uint32_t bufo = (uint32_t)(p * TILEH2 * 2);
        #pragma unroll
        for (int ks = 0; ks < 2; ks++) {
            uint32_t kx = (uint32_t)(ks << 5);
            uint32_t ah[2][4];
            #pragma unroll
            for (int mt = 0; mt < 2; mt++)
                ldsm4(ah[mt][0], ah[mt][1], ah[mt][2], ah[mt][3],
                      uA + bufo + (offA[mt] ^ kx));
            #pragma unroll
            for (int nb = 0; nb < 4; nb++) {
                uint32_t bh0, bh1, bh2, bh3;
                ldsm4(bh0, bh1, bh2, bh3, uB + bufo + (offB[nb] ^ kx));
                #pragma unroll
                for (int mt = 0; mt < 2; mt++) {
                    mma16(acc[mt][nb * 2],     ah[mt], bh0, bh1);
                    mma16(acc[mt][nb * 2 + 1], ah[mt], bh2, bh3);
                }
            }
        }
        __syncthreads();
    }

    // ---- epilogue (lane g=lane>>2, tg=lane&3; rows g,g+8; cols 2tg,2tg+1)
    int g = lane >> 2, tg = lane & 3;
    if (MODE == 0 || MODE == 1) {
        __half* Ch = (__half*)Cv;
        #pragma unroll
        for (int mt = 0; mt < 2; mt++) {
            #pragma unroll
            for (int half = 0; half < 2; half++) {
                int mr = m0 + m0w + mt * 16 + g + half * 8;
                bool v = (MODE == 0) ? true : (mr < cnt);
                if (v) {
                    long orow = (MODE == 0) ? (long)mr : (long)(base + mr);
                    __half* o = Ch + orow * 512 + jx * 64 + (n0w >> 1) + tg;
                    #pragma unroll
                    for (int nt = 0; nt < 8; nt++) {
                        float gg = acc[mt][nt][half * 2];
                        float uu = acc[mt][nt][half * 2 + 1];
                        o[nt * 4] = __float2half_rn((gg / (1.f + expf(-gg))) * uu);
                    }
                }
            }
        }
    } else if (MODE == 2) {
        float* Cf = (float*)Cv;
        #pragma unroll
        for (int mt = 0; mt < 2; mt++) {
            #pragma unroll
            for (int half = 0; half < 2; half++) {
                int mr = m0 + m0w + mt * 16 + g + half * 8;
                if (mr < cnt) {
                    int s = base + mr;
                    float* o = Cf + (long)s * 1024 + jx * 128 + n0w + 2 * tg;
                    #pragma unroll
                    for (int nt = 0; nt < 8; nt++) {
                        o[nt * 8]     = acc[mt][nt][half * 2];
                        o[nt * 8 + 1] = acc[mt][nt][half * 2 + 1];
                    }
                }
            }
        }
    } else {
        float* Cf = (float*)Cv;
        #pragma unroll
        for (int mt = 0; mt < 2; mt++) {
            #pragma unroll
            for (int half = 0; half < 2; half++) {
                int mr = m0 + m0w + mt * 16 + g + half * 8;
                float sg = g_shgate[mr];
                float* o = Cf + (long)mr * 1024 + jx * 128 + n0w + 2 * tg;
                #pragma unroll
                for (int nt = 0; nt < 8; nt++) {
                    o[nt * 8]     = sg * acc[mt][nt][half * 2];
                    o[nt * 8 + 1] = sg * acc[mt][nt][half * 2 + 1];
                }
            }
        }
    }
}

// ---------------- launch ----------------
extern "C" void kernel_launch(void* const* d_in, const int* in_sizes, int n_in,
                              void* d_out, int out_size) {
    const float* x       = (const float*)d_in[0];  // [4096,1024]
    const float* rw      = (const float*)d_in[1];  // [64,1024]
    const float* gate_up = (const float*)d_in[2];  // [64,1024,1024]
    const float* down    = (const float*)d_in[3];  // [64,1024,512]
    const float* shg     = (const float*)d_in[4];  // [512,1024]
    const float* shu     = (const float*)d_in[5];  // [512,1024]
    const float* shd     = (const float*)d_in[6];  // [1024,512]
    const float* sheg    = (const float*)d_in[7];  // [1,1024]

    float* out = (float*)d_out;
    float* probs = nullptr;
    if (out_size >= (int)(TTOK * DHID + TTOK * NEXP))
        probs = out + (size_t)TTOK * DHID;

    float *p_logits, *p_y;
    __half *p_act, *p_acts;
    cudaGetSymbolAddress((void**)&p_logits, g_logits);
    cudaGetSymbolAddress((void**)&p_y, g_y);
    cudaGetSymbolAddress((void**)&p_act, g_act);
    cudaGetSymbolAddress((void**)&p_acts, g_acts);

    const int DYN = 4 * TILEH2 * 2;  // 32768 bytes: A(2) + B(2) tiles
    cudaFuncSetAttribute(mma_gemm<0>, cudaFuncAttributeMaxDynamicSharedMemorySize, DYN);
    cudaFuncSetAttribute(mma_gemm<1>, cudaFuncAttributeMaxDynamicSharedMemorySize, DYN);
    cudaFuncSetAttribute(mma_gemm<2>, cudaFuncAttributeMaxDynamicSharedMemorySize, DYN);
    cudaFuncSetAttribute(mma_gemm<3>, cudaFuncAttributeMaxDynamicSharedMemorySize, DYN);

    // 1) router logits (fp32 SIMT — top-k selection is precision-critical)
    logits_gemm<<<dim3(1, TTOK / 32), 256>>>(x, rw, p_logits);
    // 2) softmax + top2 + shared-expert gate
    softmax_topk_kernel<<<TTOK / 8, 256>>>(x, sheg, probs);
    // 3) dispatch: histogram + scan + slot assignment
    dispatch_kernel<<<1, 1024>>>();
    // 4) shared gate/up + fused swiglu -> g_acts (fp16)
    mma_gemm<0><<<dim3(8, TTOK / 128), 256, DYN>>>(x, nullptr, shg, shu, p_acts);
    // 5) routed gate_up + fused swiglu -> g_act (fp16)
    mma_gemm<1><<<dim3(8, 2, NEXP), 256, DYN>>>(x, nullptr, gate_up, nullptr, p_act);
    // 6) shared down + sigmoid-gate -> out (fp32, full overwrite)
    mma_gemm<3><<<dim3(8, TTOK / 128), 256, DYN>>>(nullptr, p_acts, shd, nullptr, out);
    // 7) routed down -> g_y (fp32 plain stores)
    mma_gemm<2><<<dim3(8, 2, NEXP), 256, DYN>>>(nullptr, p_act, down, nullptr, p_y);
    // 8) combine: out += w0*y[s0] + w1*y[s1]
    combine_kernel<<<TTOK / 8, 256>>>(out);
}